// round 4
// baseline (speedup 1.0000x reference)
#include <cuda_runtime.h>
#include <cstdint>

// B=2,H=16,L=S=2048,D=128 fp32, causal, clip(-50,50) applied AFTER mask.
#define BH   32
#define LL   2048
#define DD   128
#define BM   128
#define BN   64
#define NQT  16          // LL/BM
#define NTHR 256

// prepass outputs: K tf32(RN)-rounded; V transposed [bh][d][s] + tf32(RN)-rounded
__device__ float g_kr[(size_t)BH * LL * DD];
__device__ float g_vt[(size_t)BH * DD * LL];

// SMEM layout (floats)
#define QS_OFF   0
#define QS_STR   132
#define KS_OFF   (QS_OFF + 128 * 132)          // 16896
#define KS_STR   132
#define VS_OFF   (KS_OFF + 64 * 132)           // 25344
#define VS_STR   68
#define VS_BUF   (128 * 68)                    // 8704 floats per buffer
#define PS_OFF   (VS_OFF + 2 * VS_BUF)         // 42752
#define PS_STR   68
#define RHO_OFF  (PS_OFF + 128 * 68)           // 51456
#define SMEM_FLOATS (RHO_OFF + 256)            // 51712
#define SMEM_BYTES  (SMEM_FLOATS * 4)          // 206848

__device__ __forceinline__ uint32_t smem_u32(const void* p) {
    uint32_t a;
    asm("{ .reg .u64 t; cvta.to.shared.u64 t, %1; cvt.u32.u64 %0, t; }" : "=r"(a) : "l"(p));
    return a;
}
#define CP_ASYNC16(dst, src) asm volatile("cp.async.cg.shared.global [%0], [%1], 16;" :: "r"(dst), "l"(src) : "memory")
#define CP_COMMIT()          asm volatile("cp.async.commit_group;" ::: "memory")
#define CP_WAIT0()           asm volatile("cp.async.wait_group 0;" ::: "memory")

__device__ __forceinline__ void ldsm_x4(uint32_t r[4], uint32_t addr) {
    asm volatile("ldmatrix.sync.aligned.m8n8.x4.shared.b16 {%0,%1,%2,%3}, [%4];"
        : "=r"(r[0]), "=r"(r[1]), "=r"(r[2]), "=r"(r[3]) : "r"(addr));
}

__device__ __forceinline__ void mma_tf32(float c[4], const uint32_t a[4], const uint32_t b[2]) {
    asm volatile(
        "mma.sync.aligned.m16n8k8.row.col.f32.tf32.tf32.f32 "
        "{%0,%1,%2,%3}, {%4,%5,%6,%7}, {%8,%9}, {%0,%1,%2,%3};"
        : "+f"(c[0]), "+f"(c[1]), "+f"(c[2]), "+f"(c[3])
        : "r"(a[0]), "r"(a[1]), "r"(a[2]), "r"(a[3]), "r"(b[0]), "r"(b[1]));
}

__device__ __forceinline__ uint32_t tf32rn(float x) {
    uint32_t u; asm("cvt.rn.tf32.f32 %0, %1;" : "=r"(u) : "f"(x)); return u;
}

// exp2(z) on the FFMA pipe, z in [-150, 0]
__device__ __forceinline__ float fexp2_poly(float z) {
    const float MAGIC = 12582912.0f;         // 1.5*2^23
    float rr = z + MAGIC;
    float f  = z - (rr - MAGIC);             // frac in [-0.5,0.5]
    float p  = 0.0013333558f;
    p = fmaf(p, f, 0.0096181291f);
    p = fmaf(p, f, 0.0555041087f);
    p = fmaf(p, f, 0.2402265069f);
    p = fmaf(p, f, 0.6931471806f);
    p = fmaf(p, f, 1.0f);
    int ir = __float_as_int(rr);
    float s1 = __int_as_float((int)(((unsigned)ir + 199u) << 23));  // 2^(n+72)
    return p * s1 * 2.1175824e-22f;          // * 2^-72
}

// ---------------------------------------------------------------------------
// Prepass A: RN-round K to tf32
__global__ void roundk_kernel(const float* __restrict__ K) {
    size_t i = (size_t)blockIdx.x * 256 + threadIdx.x;
    const float4 k4 = ((const float4*)K)[i];
    uint4 ko;
    ko.x = tf32rn(k4.x); ko.y = tf32rn(k4.y); ko.z = tf32rn(k4.z); ko.w = tf32rn(k4.w);
    ((uint4*)g_kr)[i] = ko;
}

// Prepass B: transpose + RN-round V: V[bh][s][d] -> g_vt[bh][d][s]
__global__ void vtrans_kernel(const float* __restrict__ V) {
    __shared__ float tile[32][33];
    int bh = blockIdx.z, s0 = blockIdx.x * 32, d0 = blockIdx.y * 32;
    int x = threadIdx.x;
    for (int j = threadIdx.y; j < 32; j += 8)
        tile[j][x] = V[((size_t)bh * LL + s0 + j) * DD + d0 + x];
    __syncthreads();
    for (int j = threadIdx.y; j < 32; j += 8)
        g_vt[((size_t)bh * DD + d0 + j) * LL + s0 + x] =
            __uint_as_float(tf32rn(tile[x][j]));
}

// ---------------------------------------------------------------------------
__global__ void __launch_bounds__(NTHR, 1)
attn_mma_kernel(const float* __restrict__ Q, float* __restrict__ Out)
{
    extern __shared__ float sm[];
    const int tid  = threadIdx.x;
    const int wid  = tid >> 5;
    const int lane = tid & 31;
    const int g    = lane >> 2;        // 0..7
    const int lm   = lane & 3;         // 0..3
    const int rw   = wid & 3;          // row-group
    const int cw   = wid >> 2;         // col-group
    const int rA   = rw * 32 + g;      // fragment row base (octet)
    const int cB   = cw * 32;          // score col base
    const int cV   = cw * 64;          // PV col base

    const int bidx = blockIdx.x;
    const int qt   = (NQT - 1) - (bidx >> 5);   // heavy CTAs first
    const int bh   = bidx & 31;
    const int l0   = qt * BM;
    const int tmax = 2 * qt + 1;                // kv tiles 0..tmax (BN=64)

    const float* Qg = Q + ((size_t)bh * LL + l0) * DD;
    const float* Kg = g_kr + (size_t)bh * LL * DD;
    const float* Vg = g_vt + (size_t)bh * DD * LL;   // [d][s]

    // ---- Q tile: scale by 1/sqrt(D), RN-round to tf32, store to SMEM
    {
        const float sc = 0.08838834764831845f;
#pragma unroll
        for (int i = 0; i < 16; ++i) {
            int f = i * NTHR + tid;
            int row = f >> 5, c4 = (f & 31) * 4;
            float4 v = ((const float4*)Qg)[f];
            uint4 u;
            u.x = tf32rn(v.x * sc); u.y = tf32rn(v.y * sc);
            u.z = tf32rn(v.z * sc); u.w = tf32rn(v.w * sc);
            *(uint4*)&sm[QS_OFF + row * QS_STR + c4] = u;
        }
    }

    const uint32_t suBase = smem_u32(sm);
    const uint32_t suK = suBase + KS_OFF * 4;
    const uint32_t suV = suBase + VS_OFF * 4;

    // ---- ldmatrix fragment addresses (byte addrs, hoisted)
    // A-type (Q/P): lanes 0-15 rows 0..15 (k+0), lanes 16-31 rows 0..15 (k+4)
    const int arow = rw * 32 + (lane & 15);
    const int akof = (lane >> 4) << 2;
    uint32_t qa[2], pa[2];
#pragma unroll
    for (int rt = 0; rt < 2; ++rt) {
        qa[rt] = suBase + (((arow + rt * 16) * QS_STR + akof) << 2) + QS_OFF * 4;
        pa[rt] = suBase + (((arow + rt * 16) * PS_STR + akof) << 2) + PS_OFF * 4;
    }
    // B-type (K/V): lanes 0-7 rows n0..n0+7 k+0 | 8-15 same rows k+4 |
    //               16-23 rows n0+8..15 k+0 | 24-31 rows n0+8..15 k+4
    const int brow = (lane & 7) + ((lane >> 4) << 3);
    const int bkof = ((lane >> 3) & 1) << 2;
    uint32_t kb[2], vbad[4];
#pragma unroll
    for (int np = 0; np < 2; ++np)
        kb[np] = suK + (((cB + np * 16 + brow) * KS_STR + bkof) << 2);
#pragma unroll
    for (int np = 0; np < 4; ++np)
        vbad[np] = suV + (((cV + np * 16 + brow) * VS_STR + bkof) << 2);

    // ---- prefetch K(0), V(0)
    {
#pragma unroll
        for (int i = 0; i < 8; ++i) {
            int c = i * NTHR + tid;
            int krow = c >> 5, kc4 = (c & 31) * 4;
            CP_ASYNC16(suK + (krow * KS_STR + kc4) * 4, Kg + (size_t)krow * DD + kc4);
            int vrow = c >> 4, vc4 = (c & 15) * 4;
            CP_ASYNC16(suV + (vrow * VS_STR + vc4) * 4, Vg + (size_t)vrow * LL + vc4);
        }
        CP_COMMIT();
    }

    float O[2][8][4];
#pragma unroll
    for (int rt = 0; rt < 2; ++rt)
#pragma unroll
        for (int nt = 0; nt < 8; ++nt)
#pragma unroll
            for (int c = 0; c < 4; ++c) O[rt][nt][c] = 0.f;
    float rho[2][2] = {{0.f, 0.f}, {0.f, 0.f}};

    for (int t = 0; t <= tmax; ++t) {
        const int s0 = t * BN;
        const uint32_t vboff = (uint32_t)((t & 1) * VS_BUF * 4);

        CP_WAIT0();
        __syncthreads();   // K(t), V(t) resident; prior-tile PV done

        // ---- score GEMM: S = Qtile @ Ktile^T  (tf32, ldmatrix fragments)
        float S[2][4][4];
#pragma unroll
        for (int rt = 0; rt < 2; ++rt)
#pragma unroll
            for (int nt = 0; nt < 4; ++nt)
#pragma unroll
                for (int c = 0; c < 4; ++c) S[rt][nt][c] = 0.f;

#pragma unroll
        for (int kk = 0; kk < 16; ++kk) {
            const uint32_t ko = kk * 32;     // 8 floats
            uint32_t a[2][4], b[2][4];
            ldsm_x4(a[0], qa[0] + ko);
            ldsm_x4(a[1], qa[1] + ko);
            ldsm_x4(b[0], kb[0] + ko);       // {b0,b1} of nt0 | nt1
            ldsm_x4(b[1], kb[1] + ko);       // {b0,b1} of nt2 | nt3
#pragma unroll
            for (int rt = 0; rt < 2; ++rt)
#pragma unroll
                for (int np = 0; np < 2; ++np) {
                    mma_tf32(S[rt][2 * np],     a[rt], &b[np][0]);
                    mma_tf32(S[rt][2 * np + 1], a[rt], &b[np][2]);
                }
        }
        __syncthreads();   // everyone done reading K buffer

        // ---- prefetch K(t+1), V(t+1) (overlaps softmax + PV)
        if (t < tmax) {
            const float* Kn = Kg + (size_t)(s0 + BN) * DD;
            const float* Vn = Vg + s0 + BN;
            const uint32_t suVn = suV + (uint32_t)((~t & 1) * VS_BUF * 4);
#pragma unroll
            for (int i = 0; i < 8; ++i) {
                int c = i * NTHR + tid;
                int krow = c >> 5, kc4 = (c & 31) * 4;
                CP_ASYNC16(suK + (krow * KS_STR + kc4) * 4, Kn + (size_t)krow * DD + kc4);
                int vrow = c >> 4, vc4 = (c & 15) * 4;
                CP_ASYNC16(suVn + (vrow * VS_STR + vc4) * 4, Vn + (size_t)vrow * LL + vc4);
            }
        }
        CP_COMMIT();

        // ---- softmax (fixed max = 50): p = exp2(min(s*log2e - 50*log2e, 0))
        const bool diag = (t >= 2 * qt);
#pragma unroll
        for (int rt = 0; rt < 2; ++rt) {
            float rs0 = 0.f, rs1 = 0.f;
#pragma unroll
            for (int nt = 0; nt < 4; ++nt) {
                const int colg = s0 + cB + nt * 8 + 2 * lm;
                const int rowg = l0 + rw * 32 + g + rt * 16;
                float p[4];
#pragma unroll
                for (int c = 0; c < 4; ++c) {
                    float z = fminf(fmaf(S[rt][nt][c], 1.4426950408889634f,
                                         -72.13475204444817f), 0.f);
                    float e;
                    if (c & 1) { asm("ex2.approx.f32 %0, %1;" : "=f"(e) : "f"(z)); }
                    else       { e = fexp2_poly(z); }
                    if (diag && (colg + (c & 1)) > (rowg + (c >> 1) * 8)) e = 0.f;
                    p[c] = __uint_as_float(tf32rn(e));
                }
                rs0 += p[0] + p[1];
                rs1 += p[2] + p[3];
                float* pp = &sm[PS_OFF + (rw * 32 + g + rt * 16) * PS_STR + cB + nt * 8 + 2 * lm];
                *(float2*)pp                = make_float2(p[0], p[1]);
                *(float2*)(pp + 8 * PS_STR) = make_float2(p[2], p[3]);
            }
            rs0 += __shfl_xor_sync(0xffffffffu, rs0, 1);
            rs0 += __shfl_xor_sync(0xffffffffu, rs0, 2);
            rs1 += __shfl_xor_sync(0xffffffffu, rs1, 1);
            rs1 += __shfl_xor_sync(0xffffffffu, rs1, 2);
            rho[rt][0] += rs0;
            rho[rt][1] += rs1;
        }
        __syncthreads();   // P visible to the other col-group warps

        // ---- PV GEMM: O += P @ Vtile  (tf32, ldmatrix fragments)
#pragma unroll
        for (int kk = 0; kk < 8; ++kk) {
            const uint32_t ko = kk * 32;
            uint32_t a[2][4], b[4][4];
            ldsm_x4(a[0], pa[0] + ko);
            ldsm_x4(a[1], pa[1] + ko);
#pragma unroll
            for (int np = 0; np < 4; ++np)
                ldsm_x4(b[np], vbad[np] + vboff + ko);
#pragma unroll
            for (int rt = 0; rt < 2; ++rt)
#pragma unroll
                for (int np = 0; np < 4; ++np) {
                    mma_tf32(O[rt][2 * np],     a[rt], &b[np][0]);
                    mma_tf32(O[rt][2 * np + 1], a[rt], &b[np][2]);
                }
        }
    }

    // ---- epilogue: combine rho across col-groups, normalize, store
    if (lm == 0) {
#pragma unroll
        for (int rt = 0; rt < 2; ++rt) {
            sm[RHO_OFF + cw * 128 + rA + rt * 16]     = rho[rt][0];
            sm[RHO_OFF + cw * 128 + rA + rt * 16 + 8] = rho[rt][1];
        }
    }
    __syncthreads();
#pragma unroll
    for (int rt = 0; rt < 2; ++rt) {
        const int row0 = rA + rt * 16;
        float inv0 = 1.f / (sm[RHO_OFF + row0]     + sm[RHO_OFF + 128 + row0]);
        float inv1 = 1.f / (sm[RHO_OFF + row0 + 8] + sm[RHO_OFF + 128 + row0 + 8]);
        float* o0 = Out + ((size_t)bh * LL + l0 + row0) * DD + cV + 2 * lm;
        float* o1 = o0 + 8 * DD;
#pragma unroll
        for (int nt = 0; nt < 8; ++nt) {
            *(float2*)(o0 + nt * 8) = make_float2(O[rt][nt][0] * inv0, O[rt][nt][1] * inv0);
            *(float2*)(o1 + nt * 8) = make_float2(O[rt][nt][2] * inv1, O[rt][nt][3] * inv1);
        }
    }
}

// ---------------------------------------------------------------------------
extern "C" void kernel_launch(void* const* d_in, const int* in_sizes, int n_in,
                              void* d_out, int out_size) {
    (void)in_sizes; (void)n_in; (void)out_size;
    const float* q = (const float*)d_in[0];
    const float* k = (const float*)d_in[1];
    const float* v = (const float*)d_in[2];

    roundk_kernel<<<8192, 256>>>(k);                           // 2.097M float4
    vtrans_kernel<<<dim3(LL / 32, DD / 32, BH), dim3(32, 8)>>>(v);

    cudaFuncSetAttribute(attn_mma_kernel,
                         cudaFuncAttributeMaxDynamicSharedMemorySize, SMEM_BYTES);
    attn_mma_kernel<<<NQT * BH, NTHR, SMEM_BYTES>>>(q, (float*)d_out);
}

// round 5
// speedup vs baseline: 1.0452x; 1.0452x over previous
#include <cuda_runtime.h>
#include <cstdint>

// B=2,H=16,L=S=2048,D=128 fp32, causal, clip(-50,50) applied AFTER mask.
#define BH   32
#define LL   2048
#define DD   128
#define BM   128
#define BN   64
#define NQT  16          // LL/BM
#define NTHR 256

// tf32(RN)-rounded copies of K and V
__device__ float g_kr[(size_t)BH * LL * DD];
__device__ float g_vr[(size_t)BH * LL * DD];

// SMEM layout (floats)
#define QS_OFF   0
#define QS_STR   132
#define KS_OFF   (QS_OFF + 128 * 132)          // 16896
#define KS_STR   132
#define VS_OFF   (KS_OFF + 64 * 132)           // 25344
#define VS_STR   136
#define PS_OFF   (VS_OFF + 64 * 136)           // 34048
#define PS_STR   68
#define RHO_OFF  (PS_OFF + 128 * 68)           // 42752
#define SMEM_FLOATS (RHO_OFF + 256)            // 43008
#define SMEM_BYTES  (SMEM_FLOATS * 4)          // 172032

__device__ __forceinline__ uint32_t smem_u32(const void* p) {
    uint32_t a;
    asm("{ .reg .u64 t; cvta.to.shared.u64 t, %1; cvt.u32.u64 %0, t; }" : "=r"(a) : "l"(p));
    return a;
}
#define CP_ASYNC16(dst, src) asm volatile("cp.async.cg.shared.global [%0], [%1], 16;" :: "r"(dst), "l"(src) : "memory")
#define CP_COMMIT()          asm volatile("cp.async.commit_group;" ::: "memory")
#define CP_WAIT0()           asm volatile("cp.async.wait_group 0;" ::: "memory")

__device__ __forceinline__ void mma_tf32(float c[4], const uint32_t a[4], const uint32_t b[2]) {
    asm volatile(
        "mma.sync.aligned.m16n8k8.row.col.f32.tf32.tf32.f32 "
        "{%0,%1,%2,%3}, {%4,%5,%6,%7}, {%8,%9}, {%0,%1,%2,%3};"
        : "+f"(c[0]), "+f"(c[1]), "+f"(c[2]), "+f"(c[3])
        : "r"(a[0]), "r"(a[1]), "r"(a[2]), "r"(a[3]), "r"(b[0]), "r"(b[1]));
}

__device__ __forceinline__ uint32_t tf32rn(float x) {
    uint32_t u; asm("cvt.rn.tf32.f32 %0, %1;" : "=r"(u) : "f"(x)); return u;
}

// exp2(z) on the FFMA pipe, z in [-150, 0]
__device__ __forceinline__ float fexp2_poly(float z) {
    const float MAGIC = 12582912.0f;         // 1.5*2^23
    float rr = z + MAGIC;
    float f  = z - (rr - MAGIC);             // frac in [-0.5,0.5]
    float p  = 0.0013333558f;
    p = fmaf(p, f, 0.0096181291f);
    p = fmaf(p, f, 0.0555041087f);
    p = fmaf(p, f, 0.2402265069f);
    p = fmaf(p, f, 0.6931471806f);
    p = fmaf(p, f, 1.0f);
    int ir = __float_as_int(rr);
    float s1 = __int_as_float((int)(((unsigned)ir + 199u) << 23));  // 2^(n+72)
    return p * s1 * 2.1175824e-22f;          // * 2^-72
}

// ---------------------------------------------------------------------------
// Prepass: RN-round K,V to tf32 (avoids in-MMA RZ truncation bias)
__global__ void roundkv_kernel(const float* __restrict__ K, const float* __restrict__ V) {
    size_t i = (size_t)blockIdx.x * 256 + threadIdx.x;
    const float4 k4 = ((const float4*)K)[i];
    const float4 v4 = ((const float4*)V)[i];
    uint4 ko, vo;
    ko.x = tf32rn(k4.x); ko.y = tf32rn(k4.y); ko.z = tf32rn(k4.z); ko.w = tf32rn(k4.w);
    vo.x = tf32rn(v4.x); vo.y = tf32rn(v4.y); vo.z = tf32rn(v4.z); vo.w = tf32rn(v4.w);
    ((uint4*)g_kr)[i] = ko;
    ((uint4*)g_vr)[i] = vo;
}

// ---------------------------------------------------------------------------
__global__ void __launch_bounds__(NTHR, 1)
attn_mma_kernel(const float* __restrict__ Q, float* __restrict__ Out)
{
    extern __shared__ float sm[];
    const int tid  = threadIdx.x;
    const int wid  = tid >> 5;
    const int lane = tid & 31;
    const int g    = lane >> 2;        // 0..7
    const int lm   = lane & 3;         // 0..3
    const int rw   = wid & 3;          // row-group
    const int cw   = wid >> 2;         // col-group
    const int rA   = rw * 32 + g;      // fragment row base
    const int cB   = cw * 32;          // score col base
    const int cV   = cw * 64;          // PV col base

    const int bidx = blockIdx.x;
    const int qt   = (NQT - 1) - (bidx >> 5);   // heavy CTAs first
    const int bh   = bidx & 31;
    const int l0   = qt * BM;
    const int tmax = 2 * qt + 1;                // kv tiles 0..tmax (BN=64)

    const float* Qg = Q + ((size_t)bh * LL + l0) * DD;
    const float* Kg = g_kr + (size_t)bh * LL * DD;
    const float* Vg = g_vr + (size_t)bh * LL * DD;

    // ---- Q tile: scale by 1/sqrt(D), RN-round to tf32, store to SMEM
    {
        const float sc = 0.08838834764831845f;
#pragma unroll
        for (int i = 0; i < 16; ++i) {
            int f = i * NTHR + tid;
            int row = f >> 5, c4 = (f & 31) * 4;
            float4 v = ((const float4*)Qg)[f];
            uint4 u;
            u.x = tf32rn(v.x * sc); u.y = tf32rn(v.y * sc);
            u.z = tf32rn(v.z * sc); u.w = tf32rn(v.w * sc);
            *(uint4*)&sm[QS_OFF + row * QS_STR + c4] = u;
        }
    }

    const uint32_t suK = smem_u32(&sm[KS_OFF]);
    const uint32_t suV = smem_u32(&sm[VS_OFF]);

    // ---- prefetch K(0)
#pragma unroll
    for (int i = 0; i < 8; ++i) {
        int c = i * NTHR + tid;
        int row = c >> 5, c4 = (c & 31) * 4;
        CP_ASYNC16(suK + (row * KS_STR + c4) * 4, Kg + (size_t)row * DD + c4);
    }
    CP_COMMIT();

    float O[2][8][4];
#pragma unroll
    for (int rt = 0; rt < 2; ++rt)
#pragma unroll
        for (int nt = 0; nt < 8; ++nt)
#pragma unroll
            for (int c = 0; c < 4; ++c) O[rt][nt][c] = 0.f;
    float rho[2][2] = {{0.f, 0.f}, {0.f, 0.f}};
    float S[2][4][4];

    // =======================================================================
    // Iteration t: S-MMA(t), PV-MMA(t-1), cp{K(t+1),V(t)}, softmax(t).
    // Tensor work (PV) drains while softmax issues on fma/MUFU pipes.
    // =======================================================================
    for (int t = 0; t <= tmax; ++t) {
        const int s0 = t * BN;

        CP_WAIT0();
        __syncthreads();   // K(t) & V(t-1) resident; P(t-1) fully written

        // ---- score GEMM: S = Qtile @ K(t)^T
#pragma unroll
        for (int rt = 0; rt < 2; ++rt)
#pragma unroll
            for (int nt = 0; nt < 4; ++nt)
#pragma unroll
                for (int c = 0; c < 4; ++c) S[rt][nt][c] = 0.f;
#pragma unroll
        for (int kk = 0; kk < 16; ++kk) {
            const int kc = kk * 8 + lm;
            uint32_t a[2][4], b[4][2];
#pragma unroll
            for (int rt = 0; rt < 2; ++rt) {
                const float* qp = &sm[QS_OFF + (rA + rt * 16) * QS_STR + kc];
                a[rt][0] = __float_as_uint(qp[0]);
                a[rt][1] = __float_as_uint(qp[8 * QS_STR]);
                a[rt][2] = __float_as_uint(qp[4]);
                a[rt][3] = __float_as_uint(qp[8 * QS_STR + 4]);
            }
#pragma unroll
            for (int nt = 0; nt < 4; ++nt) {
                const float* kp = &sm[KS_OFF + (cB + nt * 8 + g) * KS_STR + kc];
                b[nt][0] = __float_as_uint(kp[0]);
                b[nt][1] = __float_as_uint(kp[4]);
            }
#pragma unroll
            for (int rt = 0; rt < 2; ++rt)
#pragma unroll
                for (int nt = 0; nt < 4; ++nt)
                    mma_tf32(S[rt][nt], a[rt], b[nt]);
        }

        // ---- deferred PV GEMM: O += P(t-1) @ V(t-1)
        if (t > 0) {
#pragma unroll
            for (int kk = 0; kk < 8; ++kk) {
                const int kc = kk * 8 + lm;
                uint32_t a[2][4], b[8][2];
#pragma unroll
                for (int rt = 0; rt < 2; ++rt) {
                    const float* pp = &sm[PS_OFF + (rA + rt * 16) * PS_STR + kc];
                    a[rt][0] = __float_as_uint(pp[0]);
                    a[rt][1] = __float_as_uint(pp[8 * PS_STR]);
                    a[rt][2] = __float_as_uint(pp[4]);
                    a[rt][3] = __float_as_uint(pp[8 * PS_STR + 4]);
                }
#pragma unroll
                for (int nt = 0; nt < 8; ++nt) {
                    const float* vp = &sm[VS_OFF + kc * VS_STR + cV + nt * 8 + g];
                    b[nt][0] = __float_as_uint(vp[0]);
                    b[nt][1] = __float_as_uint(vp[4 * VS_STR]);
                }
#pragma unroll
                for (int rt = 0; rt < 2; ++rt)
#pragma unroll
                    for (int nt = 0; nt < 8; ++nt)
                        mma_tf32(O[rt][nt], a[rt], &b[nt][0]);
            }
        }
        __syncthreads();   // all reads of K(t), V(t-1), P(t-1) done

        // ---- prefetch K(t+1) and V(t) (consumed next iteration / tail)
        {
            const float* Kn = Kg + (size_t)(s0 + BN) * DD;
            const float* Vc = Vg + (size_t)s0 * DD;
            const bool doK = (t < tmax);
#pragma unroll
            for (int i = 0; i < 8; ++i) {
                int c = i * NTHR + tid;
                int row = c >> 5, c4 = (c & 31) * 4;
                if (doK)
                    CP_ASYNC16(suK + (row * KS_STR + c4) * 4, Kn + (size_t)row * DD + c4);
                CP_ASYNC16(suV + (row * VS_STR + c4) * 4, Vc + (size_t)row * DD + c4);
            }
            CP_COMMIT();
        }

        // ---- softmax(t): p = exp2(min(s*log2e - 50*log2e, 0)); overlaps PV drain
        const bool diag = (t >= 2 * qt);
#pragma unroll
        for (int rt = 0; rt < 2; ++rt) {
            float rs0 = 0.f, rs1 = 0.f;
#pragma unroll
            for (int nt = 0; nt < 4; ++nt) {
                const int colg = s0 + cB + nt * 8 + 2 * lm;
                const int rowg = l0 + rA + rt * 16;
                float p[4];
#pragma unroll
                for (int c = 0; c < 4; ++c) {
                    float z = fminf(fmaf(S[rt][nt][c], 1.4426950408889634f,
                                         -72.13475204444817f), 0.f);
                    float e;
                    if (c & 1) { asm("ex2.approx.f32 %0, %1;" : "=f"(e) : "f"(z)); }
                    else       { e = fexp2_poly(z); }
                    if (diag && (colg + (c & 1)) > (rowg + (c >> 1) * 8)) e = 0.f;
                    p[c] = __uint_as_float(tf32rn(e));
                }
                rs0 += p[0] + p[1];
                rs1 += p[2] + p[3];
                float* pp = &sm[PS_OFF + (rA + rt * 16) * PS_STR + cB + nt * 8 + 2 * lm];
                *(float2*)pp                = make_float2(p[0], p[1]);
                *(float2*)(pp + 8 * PS_STR) = make_float2(p[2], p[3]);
            }
            rs0 += __shfl_xor_sync(0xffffffffu, rs0, 1);
            rs0 += __shfl_xor_sync(0xffffffffu, rs0, 2);
            rs1 += __shfl_xor_sync(0xffffffffu, rs1, 1);
            rs1 += __shfl_xor_sync(0xffffffffu, rs1, 2);
            rho[rt][0] += rs0;
            rho[rt][1] += rs1;
        }
    }

    // ---- tail: PV-MMA(tmax)
    CP_WAIT0();
    __syncthreads();       // V(tmax) resident; P(tmax) fully written
#pragma unroll
    for (int kk = 0; kk < 8; ++kk) {
        const int kc = kk * 8 + lm;
        uint32_t a[2][4], b[8][2];
#pragma unroll
        for (int rt = 0; rt < 2; ++rt) {
            const float* pp = &sm[PS_OFF + (rA + rt * 16) * PS_STR + kc];
            a[rt][0] = __float_as_uint(pp[0]);
            a[rt][1] = __float_as_uint(pp[8 * PS_STR]);
            a[rt][2] = __float_as_uint(pp[4]);
            a[rt][3] = __float_as_uint(pp[8 * PS_STR + 4]);
        }
#pragma unroll
        for (int nt = 0; nt < 8; ++nt) {
            const float* vp = &sm[VS_OFF + kc * VS_STR + cV + nt * 8 + g];
            b[nt][0] = __float_as_uint(vp[0]);
            b[nt][1] = __float_as_uint(vp[4 * VS_STR]);
        }
#pragma unroll
        for (int rt = 0; rt < 2; ++rt)
#pragma unroll
            for (int nt = 0; nt < 8; ++nt)
                mma_tf32(O[rt][nt], a[rt], &b[nt][0]);
    }

    // ---- epilogue: combine rho across col-groups, normalize, store
    if (lm == 0) {
#pragma unroll
        for (int rt = 0; rt < 2; ++rt) {
            sm[RHO_OFF + cw * 128 + rA + rt * 16]     = rho[rt][0];
            sm[RHO_OFF + cw * 128 + rA + rt * 16 + 8] = rho[rt][1];
        }
    }
    __syncthreads();
#pragma unroll
    for (int rt = 0; rt < 2; ++rt) {
        const int row0 = rA + rt * 16;
        float inv0 = 1.f / (sm[RHO_OFF + row0]     + sm[RHO_OFF + 128 + row0]);
        float inv1 = 1.f / (sm[RHO_OFF + row0 + 8] + sm[RHO_OFF + 128 + row0 + 8]);
        float* o0 = Out + ((size_t)bh * LL + l0 + row0) * DD + cV + 2 * lm;
        float* o1 = o0 + 8 * DD;
#pragma unroll
        for (int nt = 0; nt < 8; ++nt) {
            *(float2*)(o0 + nt * 8) = make_float2(O[rt][nt][0] * inv0, O[rt][nt][1] * inv0);
            *(float2*)(o1 + nt * 8) = make_float2(O[rt][nt][2] * inv1, O[rt][nt][3] * inv1);
        }
    }
}

// ---------------------------------------------------------------------------
extern "C" void kernel_launch(void* const* d_in, const int* in_sizes, int n_in,
                              void* d_out, int out_size) {
    (void)in_sizes; (void)n_in; (void)out_size;
    const float* q = (const float*)d_in[0];
    const float* k = (const float*)d_in[1];
    const float* v = (const float*)d_in[2];

    roundkv_kernel<<<8192, 256>>>(k, v);

    cudaFuncSetAttribute(attn_mma_kernel,
                         cudaFuncAttributeMaxDynamicSharedMemorySize, SMEM_BYTES);
    attn_mma_kernel<<<NQT * BH, NTHR, SMEM_BYTES>>>(q, (float*)d_out);
}

// round 7
// speedup vs baseline: 1.5452x; 1.4784x over previous
#include <cuda_runtime.h>
#include <cuda_fp16.h>
#include <cstdint>

// B=2,H=16,L=S=2048,D=128 fp32, causal, clip(-50,50) applied AFTER mask.
#define BH   32
#define LL   2048
#define DD   128
#define BM   128
#define BN   64
#define NQT  16
#define NTHR 512

// prepass outputs: K as fp16 [s][d]; V as fp16 transposed [d][s]
__device__ __half g_kh[(size_t)BH * LL * DD];
__device__ __half g_vth[(size_t)BH * DD * LL];

// SMEM layout in HALVES
#define QS_OFF   0
#define QS_STR   136
#define KS_OFF   (128 * 136)                   // 17408
#define KS_STR   136
#define VS_OFF   (KS_OFF + 64 * 136)           // 26112
#define VS_STR   72
#define VS_BUF   (128 * 72)                    // 9216
#define PS_OFF   (VS_OFF + 2 * VS_BUF)         // 44544
#define PS_STR   72
#define RHO_OFFB ((PS_OFF + 128 * 72) * 2)     // 107520 bytes
#define SMEM_BYTES (RHO_OFFB + 512 * 4)        // 109568

__device__ __forceinline__ uint32_t smem_u32(const void* p) {
    uint32_t a;
    asm("{ .reg .u64 t; cvta.to.shared.u64 t, %1; cvt.u32.u64 %0, t; }" : "=r"(a) : "l"(p));
    return a;
}
#define CP_ASYNC16(dst, src) asm volatile("cp.async.cg.shared.global [%0], [%1], 16;" :: "r"(dst), "l"(src) : "memory")
#define CP_COMMIT()          asm volatile("cp.async.commit_group;" ::: "memory")
#define CP_WAIT0()           asm volatile("cp.async.wait_group 0;" ::: "memory")

__device__ __forceinline__ void mma_f16(float c[4], const uint32_t a[4], const uint32_t b[2]) {
    asm volatile(
        "mma.sync.aligned.m16n8k16.row.col.f32.f16.f16.f32 "
        "{%0,%1,%2,%3}, {%4,%5,%6,%7}, {%8,%9}, {%0,%1,%2,%3};"
        : "+f"(c[0]), "+f"(c[1]), "+f"(c[2]), "+f"(c[3])
        : "r"(a[0]), "r"(a[1]), "r"(a[2]), "r"(a[3]), "r"(b[0]), "r"(b[1]));
}

// exp2(z) on the FFMA pipe, valid for z in [-150, 64]
__device__ __forceinline__ float fexp2_poly(float z) {
    const float MAGIC = 12582912.0f;         // 1.5*2^23
    float rr = z + MAGIC;
    float f  = z - (rr - MAGIC);
    float p  = 0.0013333558f;
    p = fmaf(p, f, 0.0096181291f);
    p = fmaf(p, f, 0.0555041087f);
    p = fmaf(p, f, 0.2402265069f);
    p = fmaf(p, f, 0.6931471806f);
    p = fmaf(p, f, 1.0f);
    int ir = __float_as_int(rr);
    float s1 = __int_as_float((int)(((unsigned)ir + 199u) << 23));
    return p * s1 * 2.1175824e-22f;
}

// softmax rescale: p' = exp((s - Z0)); Z0=8 keeps p' inside fp16 range.
// Clamp at the reference clip point s<=50 -> z <= (50-8)*log2e.
#define LOG2E   1.4426950408889634f
#define ZOFF    (-11.541560327111707f)       // -8*log2e
#define ZCLAMP  (60.59319171733646f)         // 42*log2e
#define ZMASK   (-100.0f)

// ---------------------------------------------------------------------------
// Prepass A: K fp32 -> fp16
__global__ void halfk_kernel(const float* __restrict__ K) {
    size_t i = (size_t)blockIdx.x * 256 + threadIdx.x;
    float4 k4 = ((const float4*)K)[i];
    __half2 lo = __floats2half2_rn(k4.x, k4.y);
    __half2 hi = __floats2half2_rn(k4.z, k4.w);
    ((uint2*)g_kh)[i] = make_uint2(*(uint32_t*)&lo, *(uint32_t*)&hi);
}

// Prepass B: V fp32 [bh][s][d] -> fp16 transposed g_vth[bh][d][s]
__global__ void vtrans_kernel(const float* __restrict__ V) {
    __shared__ float tile[32][33];
    int bh = blockIdx.z, s0 = blockIdx.x * 32, d0 = blockIdx.y * 32;
    int x = threadIdx.x;
    for (int j = threadIdx.y; j < 32; j += 8)
        tile[j][x] = V[((size_t)bh * LL + s0 + j) * DD + d0 + x];
    __syncthreads();
    for (int j = threadIdx.y; j < 32; j += 8)
        g_vth[((size_t)bh * DD + d0 + j) * LL + s0 + x] = __float2half_rn(tile[x][j]);
}

// ---------------------------------------------------------------------------
__global__ void __launch_bounds__(NTHR, 1)
attn_mma_kernel(const float* __restrict__ Q, float* __restrict__ Out)
{
    extern __shared__ __half smh[];
    const int tid  = threadIdx.x;
    const int wid  = tid >> 5;
    const int lane = tid & 31;
    const int g    = lane >> 2;        // 0..7
    const int lm   = lane & 3;         // 0..3
    const int rw   = wid & 3;          // row-group 0..3
    const int cw   = wid >> 2;         // col-group 0..3
    const int rA   = rw * 32 + g;      // fragment row base
    const int cB   = cw * 16;          // score col base (16 cols per warp)
    const int cV   = cw * 32;          // PV col base  (32 cols per warp)

    const int bidx = blockIdx.x;
    const int qt   = (NQT - 1) - (bidx >> 5);   // heavy CTAs first
    const int bh   = bidx & 31;
    const int l0   = qt * BM;
    const int tmax = 2 * qt + 1;

    const float*  Qg = Q + ((size_t)bh * LL + l0) * DD;
    const __half* Kg = g_kh + (size_t)bh * LL * DD;
    const __half* Vg = g_vth + (size_t)bh * DD * LL;   // [d][s]

    // ---- Q tile: scale, convert to fp16, store to SMEM
    {
        const float sc = 0.08838834764831845f;
#pragma unroll
        for (int i = 0; i < 8; ++i) {
            int f = i * NTHR + tid;
            int row = f >> 5, c4 = (f & 31) * 4;
            float4 v = ((const float4*)Qg)[f];
            __half2 lo = __floats2half2_rn(v.x * sc, v.y * sc);
            __half2 hi = __floats2half2_rn(v.z * sc, v.w * sc);
            *(uint2*)&smh[QS_OFF + row * QS_STR + c4] =
                make_uint2(*(uint32_t*)&lo, *(uint32_t*)&hi);
        }
    }

    const uint32_t suBase = smem_u32(smh);
    const uint32_t suK = suBase + KS_OFF * 2;
    const uint32_t suV = suBase + VS_OFF * 2;

    // ---- prefetch K(0), V(0) (buf 0)
#pragma unroll
    for (int i = 0; i < 2; ++i) {
        int c = i * NTHR + tid;
        int kr = c >> 4, kc8 = (c & 15) * 8;
        CP_ASYNC16(suK + (kr * KS_STR + kc8) * 2, Kg + (size_t)kr * DD + kc8);
        int vr = c >> 3, vc8 = (c & 7) * 8;
        CP_ASYNC16(suV + (vr * VS_STR + vc8) * 2, Vg + (size_t)vr * LL + vc8);
    }
    CP_COMMIT();

    float O[2][4][4];
#pragma unroll
    for (int rt = 0; rt < 2; ++rt)
#pragma unroll
        for (int nt = 0; nt < 4; ++nt)
#pragma unroll
            for (int c = 0; c < 4; ++c) O[rt][nt][c] = 0.f;
    float rho[2][2] = {{0.f, 0.f}, {0.f, 0.f}};
    float S[2][2][4];

    for (int t = 0; t <= tmax; ++t) {
        const int s0 = t * BN;
        const int vbase = VS_OFF + (t & 1) * VS_BUF;

        CP_WAIT0();
        __syncthreads();   // K(t), V(t) resident; PV(t-1) readers of P done

        // ---- score GEMM: S = Qtile @ K(t)^T   (fp16 m16n8k16, 8 k-steps)
#pragma unroll
        for (int rt = 0; rt < 2; ++rt)
#pragma unroll
            for (int nt = 0; nt < 2; ++nt)
#pragma unroll
                for (int c = 0; c < 4; ++c) S[rt][nt][c] = 0.f;
#pragma unroll
        for (int kk = 0; kk < 8; ++kk) {
            const int kc = kk * 16 + 2 * lm;
            uint32_t a[2][4], b[2][2];
#pragma unroll
            for (int rt = 0; rt < 2; ++rt) {
                const __half* qp = &smh[QS_OFF + (rA + rt * 16) * QS_STR + kc];
                a[rt][0] = *(const uint32_t*)qp;
                a[rt][1] = *(const uint32_t*)(qp + 8 * QS_STR);
                a[rt][2] = *(const uint32_t*)(qp + 8);
                a[rt][3] = *(const uint32_t*)(qp + 8 * QS_STR + 8);
            }
#pragma unroll
            for (int nt = 0; nt < 2; ++nt) {
                const __half* kp = &smh[KS_OFF + (cB + nt * 8 + g) * KS_STR + kc];
                b[nt][0] = *(const uint32_t*)kp;
                b[nt][1] = *(const uint32_t*)(kp + 8);
            }
#pragma unroll
            for (int rt = 0; rt < 2; ++rt)
#pragma unroll
                for (int nt = 0; nt < 2; ++nt)
                    mma_f16(S[rt][nt], a[rt], b[nt]);
        }
        __syncthreads();   // K(t) readers done -> safe to overwrite K

        // ---- prefetch K(t+1) and V(t+1) (other V buffer)
        if (t < tmax) {
            const __half* Kn = Kg + (size_t)(s0 + BN) * DD;
            const __half* Vn = Vg + (s0 + BN);
            const uint32_t suVn = suV + (uint32_t)(((t + 1) & 1) * VS_BUF * 2);
#pragma unroll
            for (int i = 0; i < 2; ++i) {
                int c = i * NTHR + tid;
                int kr = c >> 4, kc8 = (c & 15) * 8;
                CP_ASYNC16(suK + (kr * KS_STR + kc8) * 2, Kn + (size_t)kr * DD + kc8);
                int vr = c >> 3, vc8 = (c & 7) * 8;
                CP_ASYNC16(suVn + (vr * VS_STR + vc8) * 2, Vn + (size_t)vr * LL + vc8);
            }
        }
        CP_COMMIT();

        // ---- softmax, rescaled: p' = exp(s - 8) (fits fp16; scale cancels)
        const bool diag = (t >= 2 * qt);
#pragma unroll
        for (int rt = 0; rt < 2; ++rt) {
            float rs0 = 0.f, rs1 = 0.f;
#pragma unroll
            for (int nt = 0; nt < 2; ++nt) {
                const int colg = s0 + cB + nt * 8 + 2 * lm;
                const int rowg = l0 + rA + rt * 16;
                float p[4];
#pragma unroll
                for (int c = 0; c < 4; ++c) {
                    float z = fminf(fmaf(S[rt][nt][c], LOG2E, ZOFF), ZCLAMP);
                    if (diag && (colg + (c & 1)) > (rowg + (c >> 1) * 8)) z = ZMASK;
                    float e;
                    if (c & 1) { asm("ex2.approx.f32 %0, %1;" : "=f"(e) : "f"(z)); }
                    else       { e = fexp2_poly(z); }
                    p[c] = e;
                }
                rs0 += p[0] + p[1];
                rs1 += p[2] + p[3];
                __half2 h01 = __floats2half2_rn(p[0], p[1]);
                __half2 h23 = __floats2half2_rn(p[2], p[3]);
                __half* pp = &smh[PS_OFF + (rA + rt * 16) * PS_STR + cB + nt * 8 + 2 * lm];
                *(__half2*)pp                = h01;
                *(__half2*)(pp + 8 * PS_STR) = h23;
            }
            rs0 += __shfl_xor_sync(0xffffffffu, rs0, 1);
            rs0 += __shfl_xor_sync(0xffffffffu, rs0, 2);
            rs1 += __shfl_xor_sync(0xffffffffu, rs1, 1);
            rs1 += __shfl_xor_sync(0xffffffffu, rs1, 2);
            rho[rt][0] += rs0;
            rho[rt][1] += rs1;
        }
        __syncthreads();   // P(t) visible to all warps

        // ---- PV GEMM: O += P(t) @ V(t)   (fp16, 4 k-steps over BN=64)
#pragma unroll
        for (int ks = 0; ks < 4; ++ks) {
            const int kc = ks * 16 + 2 * lm;
            uint32_t a[2][4], b[4][2];
#pragma unroll
            for (int rt = 0; rt < 2; ++rt) {
                const __half* pp = &smh[PS_OFF + (rA + rt * 16) * PS_STR + kc];
                a[rt][0] = *(const uint32_t*)pp;
                a[rt][1] = *(const uint32_t*)(pp + 8 * PS_STR);
                a[rt][2] = *(const uint32_t*)(pp + 8);
                a[rt][3] = *(const uint32_t*)(pp + 8 * PS_STR + 8);
            }
#pragma unroll
            for (int nt = 0; nt < 4; ++nt) {
                const __half* vp = &smh[vbase + (cV + nt * 8 + g) * VS_STR + kc];
                b[nt][0] = *(const uint32_t*)vp;
                b[nt][1] = *(const uint32_t*)(vp + 8);
            }
#pragma unroll
            for (int rt = 0; rt < 2; ++rt)
#pragma unroll
                for (int nt = 0; nt < 4; ++nt)
                    mma_f16(O[rt][nt], a[rt], b[nt]);
        }
    }

    // ---- epilogue: reduce rho across 4 col-groups, normalize, store
    float* rhof = (float*)((char*)smh + RHO_OFFB);
    if (lm == 0) {
#pragma unroll
        for (int rt = 0; rt < 2; ++rt) {
            rhof[cw * 128 + rA + rt * 16]     = rho[rt][0];
            rhof[cw * 128 + rA + rt * 16 + 8] = rho[rt][1];
        }
    }
    __syncthreads();
#pragma unroll
    for (int rt = 0; rt < 2; ++rt) {
        const int row0 = rA + rt * 16;
        float inv0 = 1.f / (rhof[row0] + rhof[128 + row0] + rhof[256 + row0] + rhof[384 + row0]);
        float inv1 = 1.f / (rhof[row0 + 8] + rhof[128 + row0 + 8] +
                            rhof[256 + row0 + 8] + rhof[384 + row0 + 8]);
        float* o0 = Out + ((size_t)bh * LL + l0 + row0) * DD + cV + 2 * lm;
        float* o1 = o0 + 8 * DD;
#pragma unroll
        for (int nt = 0; nt < 4; ++nt) {
            *(float2*)(o0 + nt * 8) = make_float2(O[rt][nt][0] * inv0, O[rt][nt][1] * inv0);
            *(float2*)(o1 + nt * 8) = make_float2(O[rt][nt][2] * inv1, O[rt][nt][3] * inv1);
        }
    }
}

// ---------------------------------------------------------------------------
extern "C" void kernel_launch(void* const* d_in, const int* in_sizes, int n_in,
                              void* d_out, int out_size) {
    (void)in_sizes; (void)n_in; (void)out_size;
    const float* q = (const float*)d_in[0];
    const float* k = (const float*)d_in[1];
    const float* v = (const float*)d_in[2];

    halfk_kernel<<<8192, 256>>>(k);
    vtrans_kernel<<<dim3(LL / 32, DD / 32, BH), dim3(32, 8)>>>(v);

    cudaFuncSetAttribute(attn_mma_kernel,
                         cudaFuncAttributeMaxDynamicSharedMemorySize, SMEM_BYTES);
    attn_mma_kernel<<<NQT * BH, NTHR, SMEM_BYTES>>>(q, (float*)d_out);
}

// round 8
// speedup vs baseline: 1.5570x; 1.0076x over previous
#include <cuda_runtime.h>
#include <cuda_fp16.h>
#include <cstdint>

// B=2,H=16,L=S=2048,D=128 fp32, causal, clip(-50,50) applied AFTER mask.
#define BH   32
#define LL   2048
#define DD   128
#define BM   128
#define BN   64
#define NQT  16
#define NTHR 512

// prepass outputs: K as fp16 [s][d]; V as fp16 transposed [d][s]
__device__ __half g_kh[(size_t)BH * LL * DD];
__device__ __half g_vth[(size_t)BH * DD * LL];

// SMEM layout in HALVES (all strides odd multiples of 16B -> ldmatrix conflict-free)
#define QS_OFF   0
#define QS_STR   136
#define KS_OFF   (128 * 136)                   // 17408
#define KS_STR   136
#define VS_OFF   (KS_OFF + 64 * 136)           // 26112
#define VS_STR   72
#define VS_BUF   (128 * 72)                    // 9216
#define PS_OFF   (VS_OFF + 2 * VS_BUF)         // 44544
#define PS_STR   72
#define RHO_OFFB ((PS_OFF + 128 * 72) * 2)     // 107520 bytes
#define SMEM_BYTES (RHO_OFFB + 512 * 4)        // 109568

__device__ __forceinline__ uint32_t smem_u32(const void* p) {
    uint32_t a;
    asm("{ .reg .u64 t; cvta.to.shared.u64 t, %1; cvt.u32.u64 %0, t; }" : "=r"(a) : "l"(p));
    return a;
}
#define CP_ASYNC16(dst, src) asm volatile("cp.async.cg.shared.global [%0], [%1], 16;" :: "r"(dst), "l"(src) : "memory")
#define CP_COMMIT()          asm volatile("cp.async.commit_group;" ::: "memory")
#define CP_WAIT0()           asm volatile("cp.async.wait_group 0;" ::: "memory")

__device__ __forceinline__ void ldsm_x4(uint32_t r[4], uint32_t addr) {
    asm volatile("ldmatrix.sync.aligned.m8n8.x4.shared.b16 {%0,%1,%2,%3}, [%4];"
        : "=r"(r[0]), "=r"(r[1]), "=r"(r[2]), "=r"(r[3]) : "r"(addr));
}

__device__ __forceinline__ void mma_f16(float c[4], const uint32_t a[4], const uint32_t b[2]) {
    asm volatile(
        "mma.sync.aligned.m16n8k16.row.col.f32.f16.f16.f32 "
        "{%0,%1,%2,%3}, {%4,%5,%6,%7}, {%8,%9}, {%0,%1,%2,%3};"
        : "+f"(c[0]), "+f"(c[1]), "+f"(c[2]), "+f"(c[3])
        : "r"(a[0]), "r"(a[1]), "r"(a[2]), "r"(a[3]), "r"(b[0]), "r"(b[1]));
}

// exp2(z) on the FFMA pipe, valid for z in [-150, 64]
__device__ __forceinline__ float fexp2_poly(float z) {
    const float MAGIC = 12582912.0f;         // 1.5*2^23
    float rr = z + MAGIC;
    float f  = z - (rr - MAGIC);
    float p  = 0.0013333558f;
    p = fmaf(p, f, 0.0096181291f);
    p = fmaf(p, f, 0.0555041087f);
    p = fmaf(p, f, 0.2402265069f);
    p = fmaf(p, f, 0.6931471806f);
    p = fmaf(p, f, 1.0f);
    int ir = __float_as_int(rr);
    float s1 = __int_as_float((int)(((unsigned)ir + 199u) << 23));
    return p * s1 * 2.1175824e-22f;
}

// softmax rescale: p' = exp(s - 8) fits fp16; scale cancels in O/rho.
#define LOG2E   1.4426950408889634f
#define ZOFF    (-11.541560327111707f)       // -8*log2e
#define ZCLAMP  (60.59319171733646f)         // (50-8)*log2e (reference clip)
#define ZMASK   (-100.0f)

// ---------------------------------------------------------------------------
// Prepass A: K fp32 -> fp16
__global__ void halfk_kernel(const float* __restrict__ K) {
    size_t i = (size_t)blockIdx.x * 256 + threadIdx.x;
    float4 k4 = ((const float4*)K)[i];
    __half2 lo = __floats2half2_rn(k4.x, k4.y);
    __half2 hi = __floats2half2_rn(k4.z, k4.w);
    ((uint2*)g_kh)[i] = make_uint2(*(uint32_t*)&lo, *(uint32_t*)&hi);
}

// Prepass B: V fp32 [bh][s][d] -> fp16 transposed g_vth[bh][d][s]
__global__ void vtrans_kernel(const float* __restrict__ V) {
    __shared__ float tile[32][33];
    int bh = blockIdx.z, s0 = blockIdx.x * 32, d0 = blockIdx.y * 32;
    int x = threadIdx.x;
    for (int j = threadIdx.y; j < 32; j += 8)
        tile[j][x] = V[((size_t)bh * LL + s0 + j) * DD + d0 + x];
    __syncthreads();
    for (int j = threadIdx.y; j < 32; j += 8)
        g_vth[((size_t)bh * DD + d0 + j) * LL + s0 + x] = __float2half_rn(tile[x][j]);
}

// ---------------------------------------------------------------------------
__global__ void __launch_bounds__(NTHR, 1)
attn_mma_kernel(const float* __restrict__ Q, float* __restrict__ Out)
{
    extern __shared__ __half smh[];
    const int tid  = threadIdx.x;
    const int wid  = tid >> 5;
    const int lane = tid & 31;
    const int g    = lane >> 2;        // 0..7
    const int lm   = lane & 3;         // 0..3
    const int rw   = wid & 3;          // row-group 0..3
    const int cw   = wid >> 2;         // col-group 0..3
    const int rA   = rw * 32 + g;      // C-fragment row base
    const int cB   = cw * 16;          // score col base (16 per warp)
    const int cV   = cw * 32;          // PV col base (32 per warp)

    const int bidx = blockIdx.x;
    const int qt   = (NQT - 1) - (bidx >> 5);   // heavy CTAs first
    const int bh   = bidx & 31;
    const int l0   = qt * BM;
    const int tmax = 2 * qt + 1;

    const float*  Qg = Q + ((size_t)bh * LL + l0) * DD;
    const __half* Kg = g_kh + (size_t)bh * LL * DD;
    const __half* Vg = g_vth + (size_t)bh * DD * LL;   // [d][s]

    // ---- Q tile: scale, convert to fp16, store to SMEM
    {
        const float sc = 0.08838834764831845f;
#pragma unroll
        for (int i = 0; i < 8; ++i) {
            int f = i * NTHR + tid;
            int row = f >> 5, c4 = (f & 31) * 4;
            float4 v = ((const float4*)Qg)[f];
            __half2 lo = __floats2half2_rn(v.x * sc, v.y * sc);
            __half2 hi = __floats2half2_rn(v.z * sc, v.w * sc);
            *(uint2*)&smh[QS_OFF + row * QS_STR + c4] =
                make_uint2(*(uint32_t*)&lo, *(uint32_t*)&hi);
        }
    }

    const uint32_t suBase = smem_u32(smh);
    const uint32_t suK = suBase + KS_OFF * 2;
    const uint32_t suV = suBase + VS_OFF * 2;

    // ---- ldmatrix per-lane source addresses (bytes), advance 32B per k-step
    // A-frag (x4): lanes 0-7: m0-7/k0 | 8-15: m8-15/k0 | 16-23: m0-7/k8 | 24-31: m8-15/k8
    const int lrow = lane & 7;
    const int arow = rw * 32 + ((lane >> 3) & 1) * 8 + lrow;
    const int akof = (lane >> 4) * 8;
    uint32_t qa[2], pa[2];
#pragma unroll
    for (int rt = 0; rt < 2; ++rt) {
        qa[rt] = suBase + ((QS_OFF + (arow + rt * 16) * QS_STR + akof) << 1);
        pa[rt] = suBase + ((PS_OFF + (arow + rt * 16) * PS_STR + akof) << 1);
    }
    // B-frag (x4): lanes 0-7: n0-7/k0 | 8-15: n0-7/k8 | 16-23: n8-15/k0 | 24-31: n8-15/k8
    const int bnrow = ((lane >> 4) & 1) * 8 + lrow;
    const int bkof  = ((lane >> 3) & 1) * 8;
    const uint32_t kba = suBase + ((KS_OFF + (cB + bnrow) * KS_STR + bkof) << 1);
    uint32_t vba[2];
#pragma unroll
    for (int np = 0; np < 2; ++np)
        vba[np] = suBase + ((VS_OFF + (cV + np * 16 + bnrow) * VS_STR + bkof) << 1);

    // ---- prefetch K(0), V(0) (buf 0)
#pragma unroll
    for (int i = 0; i < 2; ++i) {
        int c = i * NTHR + tid;
        int kr = c >> 4, kc8 = (c & 15) * 8;
        CP_ASYNC16(suK + (kr * KS_STR + kc8) * 2, Kg + (size_t)kr * DD + kc8);
        int vr = c >> 3, vc8 = (c & 7) * 8;
        CP_ASYNC16(suV + (vr * VS_STR + vc8) * 2, Vg + (size_t)vr * LL + vc8);
    }
    CP_COMMIT();

    float O[2][4][4];
#pragma unroll
    for (int rt = 0; rt < 2; ++rt)
#pragma unroll
        for (int nt = 0; nt < 4; ++nt)
#pragma unroll
            for (int c = 0; c < 4; ++c) O[rt][nt][c] = 0.f;
    float rho[2][2] = {{0.f, 0.f}, {0.f, 0.f}};
    float S[2][2][4];

    for (int t = 0; t <= tmax; ++t) {
        const int s0 = t * BN;
        const uint32_t vbuf = (uint32_t)((t & 1) * VS_BUF * 2);

        CP_WAIT0();
        __syncthreads();   // K(t), V(t) resident; PV(t-1) readers of P done

        // ---- score GEMM: S = Qtile @ K(t)^T  (ldmatrix + m16n8k16)
#pragma unroll
        for (int rt = 0; rt < 2; ++rt)
#pragma unroll
            for (int nt = 0; nt < 2; ++nt)
#pragma unroll
                for (int c = 0; c < 4; ++c) S[rt][nt][c] = 0.f;
#pragma unroll
        for (int kk = 0; kk < 8; ++kk) {
            const uint32_t ko = kk * 32;    // 16 halves
            uint32_t a[2][4], b[4];
            ldsm_x4(a[0], qa[0] + ko);
            ldsm_x4(a[1], qa[1] + ko);
            ldsm_x4(b, kba + ko);           // {nt0.b0, nt0.b1, nt1.b0, nt1.b1}
#pragma unroll
            for (int rt = 0; rt < 2; ++rt) {
                mma_f16(S[rt][0], a[rt], &b[0]);
                mma_f16(S[rt][1], a[rt], &b[2]);
            }
        }
        __syncthreads();   // K(t) readers done -> safe to overwrite K

        // ---- prefetch K(t+1) and V(t+1) (other V buffer)
        if (t < tmax) {
            const __half* Kn = Kg + (size_t)(s0 + BN) * DD;
            const __half* Vn = Vg + (s0 + BN);
            const uint32_t suVn = suV + (uint32_t)(((t + 1) & 1) * VS_BUF * 2);
#pragma unroll
            for (int i = 0; i < 2; ++i) {
                int c = i * NTHR + tid;
                int kr = c >> 4, kc8 = (c & 15) * 8;
                CP_ASYNC16(suK + (kr * KS_STR + kc8) * 2, Kn + (size_t)kr * DD + kc8);
                int vr = c >> 3, vc8 = (c & 7) * 8;
                CP_ASYNC16(suVn + (vr * VS_STR + vc8) * 2, Vn + (size_t)vr * LL + vc8);
            }
        }
        CP_COMMIT();

        // ---- softmax, rescaled: p' = exp(s - 8)
        const bool diag = (t >= 2 * qt);
#pragma unroll
        for (int rt = 0; rt < 2; ++rt) {
            float rs0 = 0.f, rs1 = 0.f;
#pragma unroll
            for (int nt = 0; nt < 2; ++nt) {
                const int colg = s0 + cB + nt * 8 + 2 * lm;
                const int rowg = l0 + rA + rt * 16;
                float p[4];
#pragma unroll
                for (int c = 0; c < 4; ++c) {
                    float z = fminf(fmaf(S[rt][nt][c], LOG2E, ZOFF), ZCLAMP);
                    if (diag && (colg + (c & 1)) > (rowg + (c >> 1) * 8)) z = ZMASK;
                    float e;
                    if (c & 1) { asm("ex2.approx.f32 %0, %1;" : "=f"(e) : "f"(z)); }
                    else       { e = fexp2_poly(z); }
                    p[c] = e;
                }
                rs0 += p[0] + p[1];
                rs1 += p[2] + p[3];
                __half2 h01 = __floats2half2_rn(p[0], p[1]);
                __half2 h23 = __floats2half2_rn(p[2], p[3]);
                __half* pp = &smh[PS_OFF + (rA + rt * 16) * PS_STR + cB + nt * 8 + 2 * lm];
                *(__half2*)pp                = h01;
                *(__half2*)(pp + 8 * PS_STR) = h23;
            }
            rs0 += __shfl_xor_sync(0xffffffffu, rs0, 1);
            rs0 += __shfl_xor_sync(0xffffffffu, rs0, 2);
            rs1 += __shfl_xor_sync(0xffffffffu, rs1, 1);
            rs1 += __shfl_xor_sync(0xffffffffu, rs1, 2);
            rho[rt][0] += rs0;
            rho[rt][1] += rs1;
        }
        __syncthreads();   // P(t) visible to all warps

        // ---- PV GEMM: O += P(t) @ V(t)  (ldmatrix + m16n8k16, 4 k-steps)
#pragma unroll
        for (int ks = 0; ks < 4; ++ks) {
            const uint32_t ko = ks * 32;
            uint32_t a[2][4], b[2][4];
            ldsm_x4(a[0], pa[0] + ko);
            ldsm_x4(a[1], pa[1] + ko);
            ldsm_x4(b[0], vba[0] + vbuf + ko);   // {nt0.b0,b1, nt1.b0,b1}
            ldsm_x4(b[1], vba[1] + vbuf + ko);   // {nt2.b0,b1, nt3.b0,b1}
#pragma unroll
            for (int rt = 0; rt < 2; ++rt)
#pragma unroll
                for (int np = 0; np < 2; ++np) {
                    mma_f16(O[rt][2 * np],     a[rt], &b[np][0]);
                    mma_f16(O[rt][2 * np + 1], a[rt], &b[np][2]);
                }
        }
    }

    // ---- epilogue: reduce rho across 4 col-groups, normalize, store
    float* rhof = (float*)((char*)smh + RHO_OFFB);
    if (lm == 0) {
#pragma unroll
        for (int rt = 0; rt < 2; ++rt) {
            rhof[cw * 128 + rA + rt * 16]     = rho[rt][0];
            rhof[cw * 128 + rA + rt * 16 + 8] = rho[rt][1];
        }
    }
    __syncthreads();
#pragma unroll
    for (int rt = 0; rt < 2; ++rt) {
        const int row0 = rA + rt * 16;
        float inv0 = 1.f / (rhof[row0] + rhof[128 + row0] + rhof[256 + row0] + rhof[384 + row0]);
        float inv1 = 1.f / (rhof[row0 + 8] + rhof[128 + row0 + 8] +
                            rhof[256 + row0 + 8] + rhof[384 + row0 + 8]);
        float* o0 = Out + ((size_t)bh * LL + l0 + row0) * DD + cV + 2 * lm;
        float* o1 = o0 + 8 * DD;
#pragma unroll
        for (int nt = 0; nt < 4; ++nt) {
            *(float2*)(o0 + nt * 8) = make_float2(O[rt][nt][0] * inv0, O[rt][nt][1] * inv0);
            *(float2*)(o1 + nt * 8) = make_float2(O[rt][nt][2] * inv1, O[rt][nt][3] * inv1);
        }
    }
}

// ---------------------------------------------------------------------------
extern "C" void kernel_launch(void* const* d_in, const int* in_sizes, int n_in,
                              void* d_out, int out_size) {
    (void)in_sizes; (void)n_in; (void)out_size;
    const float* q = (const float*)d_in[0];
    const float* k = (const float*)d_in[1];
    const float* v = (const float*)d_in[2];

    halfk_kernel<<<8192, 256>>>(k);
    vtrans_kernel<<<dim3(LL / 32, DD / 32, BH), dim3(32, 8)>>>(v);

    cudaFuncSetAttribute(attn_mma_kernel,
                         cudaFuncAttributeMaxDynamicSharedMemorySize, SMEM_BYTES);
    attn_mma_kernel<<<NQT * BH, NTHR, SMEM_BYTES>>>(q, (float*)d_out);
}

// round 9
// speedup vs baseline: 1.6683x; 1.0714x over previous
#include <cuda_runtime.h>
#include <cuda_fp16.h>
#include <cstdint>

// B=2,H=16,L=S=2048,D=128 fp32, causal, clip(-50,50) applied AFTER mask.
#define BH   32
#define LL   2048
#define DD   128
#define BM   64
#define BN   64
#define NQT  32          // LL/BM
#define NTHR 256

// prepass outputs: K as fp16 [s][d]; V as fp16 transposed [d][s]
__device__ __half g_kh[(size_t)BH * LL * DD];
__device__ __half g_vth[(size_t)BH * DD * LL];

// SMEM layout in HALVES (strides odd multiples of 16B -> ldmatrix conflict-free)
#define QS_OFF   0
#define QS_STR   136
#define KS_OFF   (64 * 136)                    // 8704
#define KS_STR   136
#define KS_BUF   (64 * 136)                    // 8704 per buffer (x2)
#define VS_OFF   (KS_OFF + 2 * KS_BUF)         // 26112
#define VS_STR   72
#define VS_BUF   (128 * 72)                    // 9216 per buffer (x2)
#define PS_OFF   (VS_OFF + 2 * VS_BUF)         // 44544
#define PS_STR   72
#define RHO_OFFB ((PS_OFF + 64 * 72) * 2)      // 98304 bytes
#define SMEM_BYTES (RHO_OFFB + 256 * 4)        // 99328

__device__ __forceinline__ uint32_t smem_u32(const void* p) {
    uint32_t a;
    asm("{ .reg .u64 t; cvta.to.shared.u64 t, %1; cvt.u32.u64 %0, t; }" : "=r"(a) : "l"(p));
    return a;
}
#define CP_ASYNC16(dst, src) asm volatile("cp.async.cg.shared.global [%0], [%1], 16;" :: "r"(dst), "l"(src) : "memory")
#define CP_COMMIT()          asm volatile("cp.async.commit_group;" ::: "memory")
#define CP_WAIT0()           asm volatile("cp.async.wait_group 0;" ::: "memory")

__device__ __forceinline__ void ldsm_x4(uint32_t r[4], uint32_t addr) {
    asm volatile("ldmatrix.sync.aligned.m8n8.x4.shared.b16 {%0,%1,%2,%3}, [%4];"
        : "=r"(r[0]), "=r"(r[1]), "=r"(r[2]), "=r"(r[3]) : "r"(addr));
}

__device__ __forceinline__ void mma_f16(float c[4], const uint32_t a[4], const uint32_t b[2]) {
    asm volatile(
        "mma.sync.aligned.m16n8k16.row.col.f32.f16.f16.f32 "
        "{%0,%1,%2,%3}, {%4,%5,%6,%7}, {%8,%9}, {%0,%1,%2,%3};"
        : "+f"(c[0]), "+f"(c[1]), "+f"(c[2]), "+f"(c[3])
        : "r"(a[0]), "r"(a[1]), "r"(a[2]), "r"(a[3]), "r"(b[0]), "r"(b[1]));
}

// exp2(z) on the FFMA pipe, valid for z in [-150, 64]
__device__ __forceinline__ float fexp2_poly(float z) {
    const float MAGIC = 12582912.0f;         // 1.5*2^23
    float rr = z + MAGIC;
    float f  = z - (rr - MAGIC);
    float p  = 0.0013333558f;
    p = fmaf(p, f, 0.0096181291f);
    p = fmaf(p, f, 0.0555041087f);
    p = fmaf(p, f, 0.2402265069f);
    p = fmaf(p, f, 0.6931471806f);
    p = fmaf(p, f, 1.0f);
    int ir = __float_as_int(rr);
    float s1 = __int_as_float((int)(((unsigned)ir + 199u) << 23));
    return p * s1 * 2.1175824e-22f;
}

// softmax rescale: p' = exp(s - 8) fits fp16; scale cancels in O/rho.
#define LOG2E   1.4426950408889634f
#define ZOFF    (-11.541560327111707f)       // -8*log2e
#define ZCLAMP  (60.59319171733646f)         // (50-8)*log2e (reference clip)
#define ZMASK   (-100.0f)

// ---------------------------------------------------------------------------
// Prepass A: K fp32 -> fp16
__global__ void halfk_kernel(const float* __restrict__ K) {
    size_t i = (size_t)blockIdx.x * 256 + threadIdx.x;
    float4 k4 = ((const float4*)K)[i];
    __half2 lo = __floats2half2_rn(k4.x, k4.y);
    __half2 hi = __floats2half2_rn(k4.z, k4.w);
    ((uint2*)g_kh)[i] = make_uint2(*(uint32_t*)&lo, *(uint32_t*)&hi);
}

// Prepass B: V fp32 [bh][s][d] -> fp16 transposed g_vth[bh][d][s]
__global__ void vtrans_kernel(const float* __restrict__ V) {
    __shared__ float tile[32][33];
    int bh = blockIdx.z, s0 = blockIdx.x * 32, d0 = blockIdx.y * 32;
    int x = threadIdx.x;
    for (int j = threadIdx.y; j < 32; j += 8)
        tile[j][x] = V[((size_t)bh * LL + s0 + j) * DD + d0 + x];
    __syncthreads();
    for (int j = threadIdx.y; j < 32; j += 8)
        g_vth[((size_t)bh * DD + d0 + j) * LL + s0 + x] = __float2half_rn(tile[x][j]);
}

// ---------------------------------------------------------------------------
__global__ void __launch_bounds__(NTHR, 2)
attn_mma_kernel(const float* __restrict__ Q, float* __restrict__ Out)
{
    extern __shared__ __half smh[];
    const int tid  = threadIdx.x;
    const int wid  = tid >> 5;
    const int lane = tid & 31;
    const int g    = lane >> 2;        // 0..7
    const int lm   = lane & 3;         // 0..3
    const int rw   = wid & 1;          // row-group 0..1
    const int cw   = wid >> 1;         // col-group 0..3
    const int rA   = rw * 32 + g;      // C-fragment row base
    const int cB   = cw * 16;          // score col base (16 per warp)
    const int cV   = cw * 32;          // PV col base (32 per warp)

    const int bidx = blockIdx.x;
    const int qt   = (NQT - 1) - (bidx >> 5);   // heavy CTAs first
    const int bh   = bidx & 31;
    const int l0   = qt * BM;

    const float*  Qg = Q + ((size_t)bh * LL + l0) * DD;
    const __half* Kg = g_kh + (size_t)bh * LL * DD;
    const __half* Vg = g_vth + (size_t)bh * DD * LL;   // [d][s]

    // ---- Q tile: scale, convert to fp16, store to SMEM (64x128)
    {
        const float sc = 0.08838834764831845f;
#pragma unroll
        for (int i = 0; i < 8; ++i) {
            int f = i * NTHR + tid;
            int row = f >> 5, c4 = (f & 31) * 4;
            float4 v = ((const float4*)Qg)[f];
            __half2 lo = __floats2half2_rn(v.x * sc, v.y * sc);
            __half2 hi = __floats2half2_rn(v.z * sc, v.w * sc);
            *(uint2*)&smh[QS_OFF + row * QS_STR + c4] =
                make_uint2(*(uint32_t*)&lo, *(uint32_t*)&hi);
        }
    }

    const uint32_t suBase = smem_u32(smh);
    const uint32_t suK = suBase + KS_OFF * 2;
    const uint32_t suV = suBase + VS_OFF * 2;

    // ---- ldmatrix per-lane source addresses (bytes)
    // A-frag (x4): lanes 0-7: m0-7/k0 | 8-15: m8-15/k0 | 16-23: m0-7/k8 | 24-31: m8-15/k8
    const int lrow = lane & 7;
    const int arow = rw * 32 + ((lane >> 3) & 1) * 8 + lrow;
    const int akof = (lane >> 4) * 8;
    uint32_t qa[2], pa[2];
#pragma unroll
    for (int rt = 0; rt < 2; ++rt) {
        qa[rt] = suBase + ((QS_OFF + (arow + rt * 16) * QS_STR + akof) << 1);
        pa[rt] = suBase + ((PS_OFF + (arow + rt * 16) * PS_STR + akof) << 1);
    }
    // B-frag (x4): lanes 0-7: n0-7/k0 | 8-15: n0-7/k8 | 16-23: n8-15/k0 | 24-31: n8-15/k8
    const int bnrow = ((lane >> 4) & 1) * 8 + lrow;
    const int bkof  = ((lane >> 3) & 1) * 8;
    const uint32_t kba = suBase + ((KS_OFF + (cB + bnrow) * KS_STR + bkof) << 1);
    uint32_t vba[2];
#pragma unroll
    for (int np = 0; np < 2; ++np)
        vba[np] = suBase + ((VS_OFF + (cV + np * 16 + bnrow) * VS_STR + bkof) << 1);

    // ---- prefetch K(0), V(0) into buffer 0
#pragma unroll
    for (int i = 0; i < 4; ++i) {
        int c = i * NTHR + tid;                     // 0..1023
        int kr = c >> 4, kc8 = (c & 15) * 8;        // K: 64 rows x 128 cols
        CP_ASYNC16(suK + (kr * KS_STR + kc8) * 2, Kg + (size_t)kr * DD + kc8);
        int vr = c >> 3, vc8 = (c & 7) * 8;         // V: 128 rows x 64 cols
        CP_ASYNC16(suV + (vr * VS_STR + vc8) * 2, Vg + (size_t)vr * LL + vc8);
    }
    CP_COMMIT();

    float O[2][4][4];
#pragma unroll
    for (int rt = 0; rt < 2; ++rt)
#pragma unroll
        for (int nt = 0; nt < 4; ++nt)
#pragma unroll
            for (int c = 0; c < 4; ++c) O[rt][nt][c] = 0.f;
    float rho[2][2] = {{0.f, 0.f}, {0.f, 0.f}};
    float S[2][2][4];

    for (int t = 0; t <= qt; ++t) {
        const int s0 = t * BN;
        const uint32_t kbuf = (uint32_t)((t & 1) * KS_BUF * 2);
        const uint32_t vbuf = (uint32_t)((t & 1) * VS_BUF * 2);

        CP_WAIT0();
        __syncthreads();   // K(t),V(t) resident; iter t-1 fully done (buffers t-1 free)

        // ---- score GEMM: S = Qtile @ K(t)^T  (ldmatrix + m16n8k16)
#pragma unroll
        for (int rt = 0; rt < 2; ++rt)
#pragma unroll
            for (int nt = 0; nt < 2; ++nt)
#pragma unroll
                for (int c = 0; c < 4; ++c) S[rt][nt][c] = 0.f;
#pragma unroll
        for (int kk = 0; kk < 8; ++kk) {
            const uint32_t ko = kk * 32;    // 16 halves
            uint32_t a[2][4], b[4];
            ldsm_x4(a[0], qa[0] + ko);
            ldsm_x4(a[1], qa[1] + ko);
            ldsm_x4(b, kba + kbuf + ko);    // {nt0.b0, nt0.b1, nt1.b0, nt1.b1}
#pragma unroll
            for (int rt = 0; rt < 2; ++rt) {
                mma_f16(S[rt][0], a[rt], &b[0]);
                mma_f16(S[rt][1], a[rt], &b[2]);
            }
        }

        // ---- prefetch K(t+1),V(t+1) into the other buffers (no sync needed:
        //      those buffers' last readers finished before the top-of-loop sync)
        if (t < qt) {
            const __half* Kn = Kg + (size_t)(s0 + BN) * DD;
            const __half* Vn = Vg + (s0 + BN);
            const uint32_t suKn = suK + (uint32_t)(((t + 1) & 1) * KS_BUF * 2);
            const uint32_t suVn = suV + (uint32_t)(((t + 1) & 1) * VS_BUF * 2);
#pragma unroll
            for (int i = 0; i < 4; ++i) {
                int c = i * NTHR + tid;
                int kr = c >> 4, kc8 = (c & 15) * 8;
                CP_ASYNC16(suKn + (kr * KS_STR + kc8) * 2, Kn + (size_t)kr * DD + kc8);
                int vr = c >> 3, vc8 = (c & 7) * 8;
                CP_ASYNC16(suVn + (vr * VS_STR + vc8) * 2, Vn + (size_t)vr * LL + vc8);
            }
            CP_COMMIT();
        }

        // ---- softmax, rescaled: p' = exp(s - 8)
        const bool diag = (t == qt);
#pragma unroll
        for (int rt = 0; rt < 2; ++rt) {
            float rs0 = 0.f, rs1 = 0.f;
#pragma unroll
            for (int nt = 0; nt < 2; ++nt) {
                const int colg = s0 + cB + nt * 8 + 2 * lm;
                const int rowg = l0 + rA + rt * 16;
                float p[4];
#pragma unroll
                for (int c = 0; c < 4; ++c) {
                    float z = fminf(fmaf(S[rt][nt][c], LOG2E, ZOFF), ZCLAMP);
                    if (diag && (colg + (c & 1)) > (rowg + (c >> 1) * 8)) z = ZMASK;
                    float e;
                    if (c & 1) { asm("ex2.approx.f32 %0, %1;" : "=f"(e) : "f"(z)); }
                    else       { e = fexp2_poly(z); }
                    p[c] = e;
                }
                rs0 += p[0] + p[1];
                rs1 += p[2] + p[3];
                __half2 h01 = __floats2half2_rn(p[0], p[1]);
                __half2 h23 = __floats2half2_rn(p[2], p[3]);
                __half* pp = &smh[PS_OFF + (rA + rt * 16) * PS_STR + cB + nt * 8 + 2 * lm];
                *(__half2*)pp                = h01;
                *(__half2*)(pp + 8 * PS_STR) = h23;
            }
            rs0 += __shfl_xor_sync(0xffffffffu, rs0, 1);
            rs0 += __shfl_xor_sync(0xffffffffu, rs0, 2);
            rs1 += __shfl_xor_sync(0xffffffffu, rs1, 1);
            rs1 += __shfl_xor_sync(0xffffffffu, rs1, 2);
            rho[rt][0] += rs0;
            rho[rt][1] += rs1;
        }
        __syncthreads();   // P(t) visible to all warps

        // ---- PV GEMM: O += P(t) @ V(t)  (ldmatrix + m16n8k16, 4 k-steps)
#pragma unroll
        for (int ks = 0; ks < 4; ++ks) {
            const uint32_t ko = ks * 32;
            uint32_t a[2][4], b[2][4];
            ldsm_x4(a[0], pa[0] + ko);
            ldsm_x4(a[1], pa[1] + ko);
            ldsm_x4(b[0], vba[0] + vbuf + ko);   // {nt0.b0,b1, nt1.b0,b1}
            ldsm_x4(b[1], vba[1] + vbuf + ko);   // {nt2.b0,b1, nt3.b0,b1}
#pragma unroll
            for (int rt = 0; rt < 2; ++rt)
#pragma unroll
                for (int np = 0; np < 2; ++np) {
                    mma_f16(O[rt][2 * np],     a[rt], &b[np][0]);
                    mma_f16(O[rt][2 * np + 1], a[rt], &b[np][2]);
                }
        }
    }

    // ---- epilogue: reduce rho across 4 col-groups, normalize, store
    float* rhof = (float*)((char*)smh + RHO_OFFB);
    if (lm == 0) {
#pragma unroll
        for (int rt = 0; rt < 2; ++rt) {
            rhof[cw * 64 + rA + rt * 16]     = rho[rt][0];
            rhof[cw * 64 + rA + rt * 16 + 8] = rho[rt][1];
        }
    }
    __syncthreads();
#pragma unroll
    for (int rt = 0; rt < 2; ++rt) {
        const int row0 = rA + rt * 16;
        float inv0 = 1.f / (rhof[row0] + rhof[64 + row0] + rhof[128 + row0] + rhof[192 + row0]);
        float inv1 = 1.f / (rhof[row0 + 8] + rhof[64 + row0 + 8] +
                            rhof[128 + row0 + 8] + rhof[192 + row0 + 8]);
        float* o0 = Out + ((size_t)bh * LL + l0 + row0) * DD + cV + 2 * lm;
        float* o1 = o0 + 8 * DD;
#pragma unroll
        for (int nt = 0; nt < 4; ++nt) {
            *(float2*)(o0 + nt * 8) = make_float2(O[rt][nt][0] * inv0, O[rt][nt][1] * inv0);
            *(float2*)(o1 + nt * 8) = make_float2(O[rt][nt][2] * inv1, O[rt][nt][3] * inv1);
        }
    }
}

// ---------------------------------------------------------------------------
extern "C" void kernel_launch(void* const* d_in, const int* in_sizes, int n_in,
                              void* d_out, int out_size) {
    (void)in_sizes; (void)n_in; (void)out_size;
    const float* q = (const float*)d_in[0];
    const float* k = (const float*)d_in[1];
    const float* v = (const float*)d_in[2];

    halfk_kernel<<<8192, 256>>>(k);
    vtrans_kernel<<<dim3(LL / 32, DD / 32, BH), dim3(32, 8)>>>(v);

    cudaFuncSetAttribute(attn_mma_kernel,
                         cudaFuncAttributeMaxDynamicSharedMemorySize, SMEM_BYTES);
    attn_mma_kernel<<<NQT * BH, NTHR, SMEM_BYTES>>>(q, (float*)d_out);
}

// round 10
// speedup vs baseline: 1.7992x; 1.0785x over previous
#include <cuda_runtime.h>
#include <cuda_fp16.h>
#include <cstdint>

// B=2,H=16,L=S=2048,D=128 fp32, causal, clip(-50,50) applied AFTER mask.
#define BH   32
#define LL   2048
#define DD   128
#define BM   64
#define BN   64
#define NQT  32          // LL/BM
#define NTHR 128         // 4 warps; each owns 16 rows

// prepass outputs: K as fp16 [s][d]; V as fp16 transposed [d][s]
__device__ __half g_kh[(size_t)BH * LL * DD];
__device__ __half g_vth[(size_t)BH * DD * LL];

// SMEM layout in HALVES (strides odd multiples of 16B -> ldmatrix conflict-free)
#define KS_OFF   0
#define KS_STR   136
#define KS_BUF   (64 * 136)                    // 8704 per buffer (x2)
#define VS_OFF   (2 * KS_BUF)                  // 17408
#define VS_STR   72
#define VS_BUF   (128 * 72)                    // 9216 per buffer (x2)
#define QST_OFF  VS_OFF                        // Q staging overlays V buf0+ (pre-loop only)
#define SMEM_HALVES (VS_OFF + 2 * VS_BUF)      // 35840
#define SMEM_BYTES  (SMEM_HALVES * 2)          // 71680

__device__ __forceinline__ uint32_t smem_u32(const void* p) {
    uint32_t a;
    asm("{ .reg .u64 t; cvta.to.shared.u64 t, %1; cvt.u32.u64 %0, t; }" : "=r"(a) : "l"(p));
    return a;
}
#define CP_ASYNC16(dst, src) asm volatile("cp.async.cg.shared.global [%0], [%1], 16;" :: "r"(dst), "l"(src) : "memory")
#define CP_COMMIT()          asm volatile("cp.async.commit_group;" ::: "memory")
#define CP_WAIT0()           asm volatile("cp.async.wait_group 0;" ::: "memory")

__device__ __forceinline__ void ldsm_x4(uint32_t r[4], uint32_t addr) {
    asm volatile("ldmatrix.sync.aligned.m8n8.x4.shared.b16 {%0,%1,%2,%3}, [%4];"
        : "=r"(r[0]), "=r"(r[1]), "=r"(r[2]), "=r"(r[3]) : "r"(addr));
}

__device__ __forceinline__ void mma_f16(float c[4], const uint32_t a[4], const uint32_t b[2]) {
    asm volatile(
        "mma.sync.aligned.m16n8k16.row.col.f32.f16.f16.f32 "
        "{%0,%1,%2,%3}, {%4,%5,%6,%7}, {%8,%9}, {%0,%1,%2,%3};"
        : "+f"(c[0]), "+f"(c[1]), "+f"(c[2]), "+f"(c[3])
        : "r"(a[0]), "r"(a[1]), "r"(a[2]), "r"(a[3]), "r"(b[0]), "r"(b[1]));
}

// exp2(z) on the FFMA pipe, valid for z in [-150, 64]
__device__ __forceinline__ float fexp2_poly(float z) {
    const float MAGIC = 12582912.0f;         // 1.5*2^23
    float rr = z + MAGIC;
    float f  = z - (rr - MAGIC);
    float p  = 0.0013333558f;
    p = fmaf(p, f, 0.0096181291f);
    p = fmaf(p, f, 0.0555041087f);
    p = fmaf(p, f, 0.2402265069f);
    p = fmaf(p, f, 0.6931471806f);
    p = fmaf(p, f, 1.0f);
    int ir = __float_as_int(rr);
    float s1 = __int_as_float((int)(((unsigned)ir + 199u) << 23));
    return p * s1 * 2.1175824e-22f;
}

// softmax rescale: p' = exp(s - 8) fits fp16; scale cancels in O/rho.
#define LOG2E   1.4426950408889634f
#define ZOFF    (-11.541560327111707f)       // -8*log2e
#define ZCLAMP  (60.59319171733646f)         // (50-8)*log2e (reference clip)
#define ZMASK   (-100.0f)

// ---------------------------------------------------------------------------
// Fused prepass: K fp32->fp16 (same layout) and V fp32->fp16 transposed [d][s]
__global__ void prep_kernel(const float* __restrict__ K, const float* __restrict__ V) {
    __shared__ float tile[32][33];
    int bh = blockIdx.z, s0 = blockIdx.x * 32, d0 = blockIdx.y * 32;
    int x = threadIdx.x;
    for (int j = threadIdx.y; j < 32; j += 8) {
        size_t idx = ((size_t)bh * LL + s0 + j) * DD + d0 + x;
        g_kh[idx] = __float2half_rn(K[idx]);
        tile[j][x] = V[idx];
    }
    __syncthreads();
    for (int j = threadIdx.y; j < 32; j += 8)
        g_vth[((size_t)bh * DD + d0 + j) * LL + s0 + x] = __float2half_rn(tile[x][j]);
}

// ---------------------------------------------------------------------------
__global__ void __launch_bounds__(NTHR, 3)
attn_mma_kernel(const float* __restrict__ Q, float* __restrict__ Out)
{
    extern __shared__ __half smh[];
    const int tid  = threadIdx.x;
    const int wid  = tid >> 5;         // 0..3, owns rows [16*wid, 16*wid+16)
    const int lane = tid & 31;
    const int g    = lane >> 2;        // 0..7
    const int lm   = lane & 3;         // 0..3
    const int lrow = lane & 7;
    const int wr   = wid * 16;

    const int bidx = blockIdx.x;
    const int qt   = (NQT - 1) - (bidx >> 5);   // heavy CTAs first
    const int bh   = bidx & 31;
    const int l0   = qt * BM;

    const float*  Qg = Q + ((size_t)bh * LL + l0) * DD;
    const __half* Kg = g_kh + (size_t)bh * LL * DD;
    const __half* Vg = g_vth + (size_t)bh * DD * LL;   // [d][s]

    const uint32_t suBase = smem_u32(smh);
    const uint32_t suK = suBase + KS_OFF * 2;
    const uint32_t suV = suBase + VS_OFF * 2;

    // ---- stage Q (64x128) -> smem (V-buf area, pre-loop only), fp16, scaled
    {
        const float sc = 0.08838834764831845f;
#pragma unroll
        for (int i = 0; i < 16; ++i) {
            int f = i * NTHR + tid;
            int row = f >> 5, c4 = (f & 31) * 4;
            float4 v = ((const float4*)Qg)[f];
            __half2 lo = __floats2half2_rn(v.x * sc, v.y * sc);
            __half2 hi = __floats2half2_rn(v.z * sc, v.w * sc);
            *(uint2*)&smh[QST_OFF + row * 136 + c4] =
                make_uint2(*(uint32_t*)&lo, *(uint32_t*)&hi);
        }
    }
    __syncthreads();

    // ---- Q A-fragments -> registers (held for entire kernel)
    // x4 map: lanes 0-7: m0-7/k0 | 8-15: m8-15/k0 | 16-23: m0-7/k8 | 24-31: m8-15/k8
    uint32_t qr[8][4];
    {
        const int arow = wr + ((lane >> 3) & 1) * 8 + lrow;
        const int akof = (lane >> 4) * 8;
        const uint32_t qa = suBase + ((QST_OFF + arow * 136 + akof) << 1);
#pragma unroll
        for (int kk = 0; kk < 8; ++kk)
            ldsm_x4(qr[kk], qa + kk * 32);
    }
    __syncthreads();   // all warps done reading staging before V(0) overwrites it

    // ---- B-fragment lane addressing
    // x4 map: lanes 0-7: n0-7/k0 | 8-15: n0-7/k8 | 16-23: n8-15/k0 | 24-31: n8-15/k8
    const int bnrow = ((lane >> 4) & 1) * 8 + lrow;
    const int bkof  = ((lane >> 3) & 1) * 8;
    uint32_t kb[4], vb[8];
#pragma unroll
    for (int j = 0; j < 4; ++j)
        kb[j] = suK + ((16 * j + bnrow) * KS_STR + bkof) * 2;
#pragma unroll
    for (int j = 0; j < 8; ++j)
        vb[j] = suV + ((16 * j + bnrow) * VS_STR + bkof) * 2;

    // ---- prefetch K(0), V(0) into buffer 0
#pragma unroll
    for (int i = 0; i < 8; ++i) {
        int c = i * NTHR + tid;                     // 0..1023
        int kr = c >> 4, kc8 = (c & 15) * 8;        // K: 64 x 128
        CP_ASYNC16(suK + (kr * KS_STR + kc8) * 2, Kg + (size_t)kr * DD + kc8);
        int vr = c >> 3, vc8 = (c & 7) * 8;         // V: 128 x 64
        CP_ASYNC16(suV + (vr * VS_STR + vc8) * 2, Vg + (size_t)vr * LL + vc8);
    }
    CP_COMMIT();

    float O[16][4];
#pragma unroll
    for (int nt = 0; nt < 16; ++nt)
#pragma unroll
        for (int c = 0; c < 4; ++c) O[nt][c] = 0.f;
    float rho0 = 0.f, rho1 = 0.f;

    const int rowg = l0 + wr + g;      // this thread's even row (odd = +8)

    for (int t = 0; t <= qt; ++t) {
        const int s0 = t * BN;
        const uint32_t kbuf = (uint32_t)((t & 1) * KS_BUF * 2);
        const uint32_t vbuf = (uint32_t)((t & 1) * VS_BUF * 2);

        CP_WAIT0();
        __syncthreads();   // K(t),V(t) resident; t-1 consumers of other bufs done

        // ---- score GEMM: S(16x64) = Qrows @ K(t)^T  (Q in regs, K via ldsm)
        float S[8][4];
#pragma unroll
        for (int nt = 0; nt < 8; ++nt)
#pragma unroll
            for (int c = 0; c < 4; ++c) S[nt][c] = 0.f;
#pragma unroll
        for (int kk = 0; kk < 8; ++kk) {
            const uint32_t ko = kk * 32;
#pragma unroll
            for (int j = 0; j < 4; ++j) {
                uint32_t b[4];
                ldsm_x4(b, kb[j] + kbuf + ko);
                mma_f16(S[2 * j],     qr[kk], &b[0]);
                mma_f16(S[2 * j + 1], qr[kk], &b[2]);
            }
        }

        // ---- prefetch K(t+1),V(t+1) into the other buffers
        if (t < qt) {
            const __half* Kn = Kg + (size_t)(s0 + BN) * DD;
            const __half* Vn = Vg + (s0 + BN);
            const uint32_t suKn = suK + (uint32_t)((~t & 1) * KS_BUF * 2);
            const uint32_t suVn = suV + (uint32_t)((~t & 1) * VS_BUF * 2);
#pragma unroll
            for (int i = 0; i < 8; ++i) {
                int c = i * NTHR + tid;
                int kr = c >> 4, kc8 = (c & 15) * 8;
                CP_ASYNC16(suKn + (kr * KS_STR + kc8) * 2, Kn + (size_t)kr * DD + kc8);
                int vr = c >> 3, vc8 = (c & 7) * 8;
                CP_ASYNC16(suVn + (vr * VS_STR + vc8) * 2, Vn + (size_t)vr * LL + vc8);
            }
            CP_COMMIT();
        }

        // ---- softmax in registers: p' = exp(s - 8); P stays as A-fragments
        const bool diag = (t == qt);
        uint32_t pl[8], ph[8];     // pl[nt]=half2(c0,c1), ph[nt]=half2(c2,c3)
        float rs0 = 0.f, rs1 = 0.f;
#pragma unroll
        for (int nt = 0; nt < 8; ++nt) {
            const int colg = s0 + 8 * nt + 2 * lm;
            float p[4];
#pragma unroll
            for (int c = 0; c < 4; ++c) {
                float z = fminf(fmaf(S[nt][c], LOG2E, ZOFF), ZCLAMP);
                if (diag && (colg + (c & 1)) > (rowg + (c >> 1) * 8)) z = ZMASK;
                float e;
                if (c & 1) { asm("ex2.approx.f32 %0, %1;" : "=f"(e) : "f"(z)); }
                else       { e = fexp2_poly(z); }
                p[c] = e;
            }
            rs0 += p[0] + p[1];
            rs1 += p[2] + p[3];
            __half2 h01 = __floats2half2_rn(p[0], p[1]);
            __half2 h23 = __floats2half2_rn(p[2], p[3]);
            pl[nt] = *(uint32_t*)&h01;
            ph[nt] = *(uint32_t*)&h23;
        }
        rs0 += __shfl_xor_sync(0xffffffffu, rs0, 1);
        rs0 += __shfl_xor_sync(0xffffffffu, rs0, 2);
        rs1 += __shfl_xor_sync(0xffffffffu, rs1, 1);
        rs1 += __shfl_xor_sync(0xffffffffu, rs1, 2);
        rho0 += rs0;
        rho1 += rs1;

        // ---- PV GEMM: O(16x128) += P(regs) @ V(t)  (C-frag == A-frag trick)
#pragma unroll
        for (int ks = 0; ks < 4; ++ks) {
            const uint32_t ko = ks * 32;
            const uint32_t a[4] = { pl[2 * ks], ph[2 * ks],
                                    pl[2 * ks + 1], ph[2 * ks + 1] };
#pragma unroll
            for (int j = 0; j < 8; ++j) {
                uint32_t b[4];
                ldsm_x4(b, vb[j] + vbuf + ko);
                mma_f16(O[2 * j],     a, &b[0]);
                mma_f16(O[2 * j + 1], a, &b[2]);
            }
        }
    }

    // ---- epilogue: fully warp-local normalize + store (no barrier)
    const float inv0 = 1.f / rho0;
    const float inv1 = 1.f / rho1;
    float* o0 = Out + ((size_t)bh * LL + rowg) * DD + 2 * lm;
    float* o1 = o0 + 8 * DD;
#pragma unroll
    for (int nt = 0; nt < 16; ++nt) {
        *(float2*)(o0 + 8 * nt) = make_float2(O[nt][0] * inv0, O[nt][1] * inv0);
        *(float2*)(o1 + 8 * nt) = make_float2(O[nt][2] * inv1, O[nt][3] * inv1);
    }
}

// ---------------------------------------------------------------------------
extern "C" void kernel_launch(void* const* d_in, const int* in_sizes, int n_in,
                              void* d_out, int out_size) {
    (void)in_sizes; (void)n_in; (void)out_size;
    const float* q = (const float*)d_in[0];
    const float* k = (const float*)d_in[1];
    const float* v = (const float*)d_in[2];

    prep_kernel<<<dim3(LL / 32, DD / 32, BH), dim3(32, 8)>>>(k, v);

    cudaFuncSetAttribute(attn_mma_kernel,
                         cudaFuncAttributeMaxDynamicSharedMemorySize, SMEM_BYTES);
    attn_mma_kernel<<<NQT * BH, NTHR, SMEM_BYTES>>>(q, (float*)d_out);
}